// round 1
// baseline (speedup 1.0000x reference)
#include <cuda_runtime.h>
#include <cuda_bf16.h>

// Problem constants
#define BB 2
#define LL 2048
#define DM 1024
#define NH 16
#define HD 64
// total rows = B*L = 4096

// Scratch (allocation-free rule: __device__ globals)
__device__ float g_Q[BB * LL * DM];
__device__ float g_K[BB * LL * DM];
__device__ float g_V[BB * LL * DM];
__device__ float g_attn[BB * LL * DM];
__device__ float g_M[BB * NH * HD * HD];

// ---------------------------------------------------------------------------
// SGEMM: C[M,N] = A[M,K] @ W[K,N] + bias[N]
// M=4096, N=1024, K=1024 fixed. 128x128 block tile, BK=8, 8x8 per thread.
// ---------------------------------------------------------------------------
__global__ void __launch_bounds__(256) sgemm_bias_kernel(
    const float* __restrict__ A, const float* __restrict__ Wt,
    const float* __restrict__ bias, float* __restrict__ C)
{
    const int M = 4096, N = 1024, K = 1024;
    const int BM = 128, BN = 128, BK = 8, TM = 8, TN = 8;
    (void)M;

    __shared__ float As[BK][BM];
    __shared__ float Bs[BK][BN];

    const int tid = threadIdx.x;
    const int tx = tid & 15;        // 0..15 -> column group
    const int ty = tid >> 4;        // 0..15 -> row group

    // A-tile load mapping: 128 rows x 8 cols, one float4 per thread
    const int aRow = tid >> 1;          // 0..127
    const int aCol = (tid & 1) * 4;     // 0 or 4
    // B-tile load mapping: 8 rows x 128 cols, one float4 per thread
    const int bRow = tid >> 5;          // 0..7
    const int bCol = (tid & 31) * 4;    // 0..124

    const float* Ab = A + (size_t)blockIdx.y * BM * K;
    const float* Bb = Wt + (size_t)blockIdx.x * BN;

    float acc[TM][TN];
#pragma unroll
    for (int i = 0; i < TM; i++)
#pragma unroll
        for (int j = 0; j < TN; j++) acc[i][j] = 0.f;

    for (int k0 = 0; k0 < K; k0 += BK) {
        float4 av = *(const float4*)(Ab + (size_t)aRow * K + k0 + aCol);
        As[aCol + 0][aRow] = av.x;
        As[aCol + 1][aRow] = av.y;
        As[aCol + 2][aRow] = av.z;
        As[aCol + 3][aRow] = av.w;
        float4 bv = *(const float4*)(Bb + (size_t)(k0 + bRow) * N + bCol);
        *(float4*)(&Bs[bRow][bCol]) = bv;
        __syncthreads();

#pragma unroll
        for (int kk = 0; kk < BK; kk++) {
            float ar[TM], br[TN];
#pragma unroll
            for (int i = 0; i < TM; i++) ar[i] = As[kk][ty * TM + i];
#pragma unroll
            for (int j = 0; j < TN; j++) br[j] = Bs[kk][tx * TN + j];
#pragma unroll
            for (int i = 0; i < TM; i++)
#pragma unroll
                for (int j = 0; j < TN; j++)
                    acc[i][j] = fmaf(ar[i], br[j], acc[i][j]);
        }
        __syncthreads();
    }

    const int cRow0 = blockIdx.y * BM + ty * TM;
    const int cCol0 = blockIdx.x * BN + tx * TN;
#pragma unroll
    for (int i = 0; i < TM; i++) {
        float* crow = C + (size_t)(cRow0 + i) * N + cCol0;
#pragma unroll
        for (int j = 0; j < TN; j += 4) {
            float4 o;
            o.x = acc[i][j + 0] + bias[cCol0 + j + 0];
            o.y = acc[i][j + 1] + bias[cCol0 + j + 1];
            o.z = acc[i][j + 2] + bias[cCol0 + j + 2];
            o.w = acc[i][j + 3] + bias[cCol0 + j + 3];
            *(float4*)(crow + j) = o;
        }
    }
}

// ---------------------------------------------------------------------------
// kv_outer: M[b,h] = scale * K_slice^T @ V_slice  ([64,2048]^T-view x [2048,64])
// One block per (b,h). 256 threads, 4x4 micro-tile each.
// ---------------------------------------------------------------------------
__global__ void __launch_bounds__(256) kv_outer_kernel()
{
    const int bh = blockIdx.x;          // 0..31
    const int b = bh >> 4;
    const int h = bh & 15;

    __shared__ float Ks[64][65];
    __shared__ float Vs[64][65];

    const int tid = threadIdx.x;
    const int tx = tid & 15;
    const int ty = tid >> 4;

    const float* Kb = g_K + (size_t)b * LL * DM + h * HD;
    const float* Vb = g_V + (size_t)b * LL * DM + h * HD;

    float acc[4][4];
#pragma unroll
    for (int i = 0; i < 4; i++)
#pragma unroll
        for (int j = 0; j < 4; j++) acc[i][j] = 0.f;

    for (int l0 = 0; l0 < LL; l0 += 64) {
        // load 64x64 of K and V (each thread: 4 float4s per tensor)
#pragma unroll
        for (int t = 0; t < 4; t++) {
            int idx = tid + t * 256;        // 0..1023 float4 slots
            int r = idx >> 4;               // 0..63
            int c = (idx & 15) * 4;         // 0..60
            float4 kv = *(const float4*)(Kb + (size_t)(l0 + r) * DM + c);
            Ks[r][c + 0] = kv.x; Ks[r][c + 1] = kv.y;
            Ks[r][c + 2] = kv.z; Ks[r][c + 3] = kv.w;
            float4 vv = *(const float4*)(Vb + (size_t)(l0 + r) * DM + c);
            Vs[r][c + 0] = vv.x; Vs[r][c + 1] = vv.y;
            Vs[r][c + 2] = vv.z; Vs[r][c + 3] = vv.w;
        }
        __syncthreads();

#pragma unroll 8
        for (int l = 0; l < 64; l++) {
            float kr[4], vr[4];
#pragma unroll
            for (int i = 0; i < 4; i++) kr[i] = Ks[l][ty * 4 + i];
#pragma unroll
            for (int j = 0; j < 4; j++) vr[j] = Vs[l][tx * 4 + j];
#pragma unroll
            for (int i = 0; i < 4; i++)
#pragma unroll
                for (int j = 0; j < 4; j++)
                    acc[i][j] = fmaf(kr[i], vr[j], acc[i][j]);
        }
        __syncthreads();
    }

    const float scale = 0.125f;  // 1/sqrt(64)
    float* Mo = g_M + (size_t)bh * HD * HD;
#pragma unroll
    for (int i = 0; i < 4; i++)
#pragma unroll
        for (int j = 0; j < 4; j++)
            Mo[(ty * 4 + i) * HD + tx * 4 + j] = acc[i][j] * scale;
}

// ---------------------------------------------------------------------------
// attn_apply: attn[b, l, h, :] = Q[b, l, h, :] @ M[b,h]   (64-dim x 64x64)
// grid: (L/64, B*NH). Block 256 threads: 64 rows, 4 threads/row x 16 cols.
// ---------------------------------------------------------------------------
__global__ void __launch_bounds__(256) attn_apply_kernel()
{
    const int bh = blockIdx.y;
    const int b = bh >> 4;
    const int h = bh & 15;
    const int l0 = blockIdx.x * 64;

    __shared__ float Ms[64][65];
    __shared__ float Qs[64][65];

    const int tid = threadIdx.x;
    const float* Mg = g_M + (size_t)bh * HD * HD;
    const float* Qb = g_Q + ((size_t)b * LL + l0) * DM + h * HD;

#pragma unroll
    for (int t = 0; t < 4; t++) {
        int idx = tid + t * 256;
        int r = idx >> 4;
        int c = (idx & 15) * 4;
        float4 mv = *(const float4*)(Mg + r * HD + c);
        Ms[r][c + 0] = mv.x; Ms[r][c + 1] = mv.y;
        Ms[r][c + 2] = mv.z; Ms[r][c + 3] = mv.w;
        float4 qv = *(const float4*)(Qb + (size_t)r * DM + c);
        Qs[r][c + 0] = qv.x; Qs[r][c + 1] = qv.y;
        Qs[r][c + 2] = qv.z; Qs[r][c + 3] = qv.w;
    }
    __syncthreads();

    const int row = tid >> 2;           // 0..63
    const int c0 = (tid & 3) * 16;      // 0,16,32,48

    float acc[16];
#pragma unroll
    for (int j = 0; j < 16; j++) acc[j] = 0.f;

#pragma unroll 8
    for (int k = 0; k < 64; k++) {
        float q = Qs[row][k];
#pragma unroll
        for (int j = 0; j < 16; j++)
            acc[j] = fmaf(q, Ms[k][c0 + j], acc[j]);
    }

    float* Ao = g_attn + ((size_t)b * LL + l0 + row) * DM + h * HD + c0;
#pragma unroll
    for (int j = 0; j < 16; j += 4) {
        float4 o = make_float4(acc[j], acc[j + 1], acc[j + 2], acc[j + 3]);
        *(float4*)(Ao + j) = o;
    }
}

// ---------------------------------------------------------------------------
extern "C" void kernel_launch(void* const* d_in, const int* in_sizes, int n_in,
                              void* d_out, int out_size)
{
    (void)in_sizes; (void)n_in; (void)out_size;
    const float* x  = (const float*)d_in[0];
    const float* Wq = (const float*)d_in[1];
    const float* bq = (const float*)d_in[2];
    const float* Wk = (const float*)d_in[3];
    const float* bk = (const float*)d_in[4];
    const float* Wv = (const float*)d_in[5];
    const float* bv = (const float*)d_in[6];
    const float* Wo = (const float*)d_in[7];
    const float* bo = (const float*)d_in[8];
    float* out = (float*)d_out;

    float *Q, *K, *V, *attn;
    cudaGetSymbolAddress((void**)&Q, g_Q);
    cudaGetSymbolAddress((void**)&K, g_K);
    cudaGetSymbolAddress((void**)&V, g_V);
    cudaGetSymbolAddress((void**)&attn, g_attn);

    dim3 gemm_grid(1024 / 128, 4096 / 128);  // (8, 32)
    dim3 gemm_blk(256);

    // QKV projections
    sgemm_bias_kernel<<<gemm_grid, gemm_blk>>>(x, Wq, bq, Q);
    sgemm_bias_kernel<<<gemm_grid, gemm_blk>>>(x, Wk, bk, K);
    sgemm_bias_kernel<<<gemm_grid, gemm_blk>>>(x, Wv, bv, V);

    // M[b,h] = scale * K^T V   (linear attention reassociation)
    kv_outer_kernel<<<BB * NH, 256>>>();

    // attn = Q @ M
    dim3 attn_grid(LL / 64, BB * NH);
    attn_apply_kernel<<<attn_grid, 256>>>();

    // out = attn @ Wo + bo
    sgemm_bias_kernel<<<gemm_grid, gemm_blk>>>(attn, Wo, bo, out);
}

// round 6
// speedup vs baseline: 2.7041x; 2.7041x over previous
#include <cuda_runtime.h>
#include <cuda_bf16.h>
#include <cstdint>

#define BB 2
#define LL 2048
#define DM 1024
#define NH 16
#define HD 64
#define ROWS (BB*LL)      /* 4096 */
#define NQKV (3*DM)       /* 3072 */

// ---------------- device scratch (allocation-free rule) ----------------
__device__ __nv_bfloat16 g_xh[ROWS*DM];
__device__ __nv_bfloat16 g_xl[ROWS*DM];
__device__ __nv_bfloat16 g_Wth[NQKV*DM];   // [Wq^T;Wk^T;Wv^T] as [n][k]
__device__ __nv_bfloat16 g_Wtl[NQKV*DM];
__device__ __nv_bfloat16 g_Woth[DM*DM];    // Wo^T [n][k]
__device__ __nv_bfloat16 g_Wotl[DM*DM];
__device__ float g_QKV[ROWS*NQKV];         // fused QKV output, fp32
__device__ float g_biasqkv[NQKV];
__device__ float g_Mp[8*BB*NH*HD*HD];      // kv partials [ls][bh][64][64]
__device__ float g_M[BB*NH*HD*HD];
__device__ __nv_bfloat16 g_ah[ROWS*DM];    // attn hi/lo
__device__ __nv_bfloat16 g_al[ROWS*DM];

// ---------------- helpers ----------------
__device__ __forceinline__ uint32_t s2u(const void* p) {
    uint32_t a;
    asm("{ .reg .u64 t; cvta.to.shared.u64 t, %1; cvt.u32.u64 %0, t; }" : "=r"(a) : "l"(p));
    return a;
}
#define SWZ(x) ((x) ^ (((x) >> 3) & 0x70))

__device__ __forceinline__ void cpa16(uint32_t dst, const void* src) {
    asm volatile("cp.async.cg.shared.global [%0], [%1], 16;" :: "r"(dst), "l"(src));
}

__device__ __forceinline__ void ldsm_x4(uint32_t& r0, uint32_t& r1, uint32_t& r2,
                                        uint32_t& r3, uint32_t addr) {
    asm volatile("ldmatrix.sync.aligned.m8n8.x4.shared.b16 {%0,%1,%2,%3}, [%4];"
                 : "=r"(r0), "=r"(r1), "=r"(r2), "=r"(r3) : "r"(addr));
}

__device__ __forceinline__ void mma16816(float* d, const uint32_t* a, const uint32_t* b) {
    asm volatile(
        "mma.sync.aligned.m16n8k16.row.col.f32.bf16.bf16.f32 "
        "{%0,%1,%2,%3}, {%4,%5,%6,%7}, {%8,%9}, {%0,%1,%2,%3};"
        : "+f"(d[0]), "+f"(d[1]), "+f"(d[2]), "+f"(d[3])
        : "r"(a[0]), "r"(a[1]), "r"(a[2]), "r"(a[3]), "r"(b[0]), "r"(b[1]));
}

// ---------------- bf16x3 HMMA GEMM ----------------
// C[M,N] = Ah@Bh^T + Ah@Bl^T + Al@Bh^T + bias, fp32 out.
// A: [M][1024] bf16 row-major; B: [N][1024] bf16 row-major (N rows, K cols).
// CTA 128x128, BK=64, 8 warps (2x4), warp tile 64x32, double-buffered cp.async.
#define TILE_B 16384u                       /* 128 rows x 128 bytes */
#define STAGE_B (4u*TILE_B)                 /* Ah, Al, Bh, Bl */
#define SMEM_GEMM_TOTAL (2*STAGE_B)         /* 131072 */
#define NIT 16

__global__ void __launch_bounds__(256, 1)
gemm_bf16x3(const __nv_bfloat16* __restrict__ Ah, const __nv_bfloat16* __restrict__ Al,
            const __nv_bfloat16* __restrict__ Bh, const __nv_bfloat16* __restrict__ Bl,
            const float* __restrict__ bias, float* __restrict__ C, int ldc)
{
    extern __shared__ char smem[];
    const uint32_t sbase = s2u(smem);
    const int tid = threadIdx.x;
    const int wid = tid >> 5, lane = tid & 31;
    const int wm = wid >> 2;          // 0..1 (m)
    const int wn = wid & 3;           // 0..3 (n)
    const int m0 = blockIdx.y * 128;
    const int n0 = blockIdx.x * 128;

    // ---- stage loader: 4 tiles (Ah, Al, Bh, Bl), 16 cp.async per thread ----
    auto load_stage = [&](int it) {
        uint32_t stage = sbase + (uint32_t)(it & 1) * STAGE_B;
        const int k0 = it * 64;
        const __nv_bfloat16* bases[4] = {Ah, Al, Bh, Bl};
        const int r0[4] = {m0, m0, n0, n0};
#pragma unroll
        for (int t = 0; t < 4; t++) {
#pragma unroll
            for (int j = 0; j < 4; j++) {
                int u = tid + j * 256;          // 0..1023 16B-chunks
                int row = u >> 3;
                int cb = (u & 7) * 16;          // byte col within 128B row
                const char* src = (const char*)(bases[t] + (size_t)(r0[t] + row) * DM + k0)
                                  + cb;
                uint32_t dst = stage + (uint32_t)t * TILE_B + SWZ((uint32_t)(row * 128 + cb));
                cpa16(dst, src);
            }
        }
        asm volatile("cp.async.commit_group;");
    };

    load_stage(0);
    load_stage(1);

    float acc[4][4][4];
#pragma unroll
    for (int i = 0; i < 4; i++)
#pragma unroll
        for (int j = 0; j < 4; j++)
#pragma unroll
            for (int e = 0; e < 4; e++) acc[i][j][e] = 0.f;

    // precompute per-lane row-byte offsets (k-independent part)
    uint32_t aRB[4], bRB[2];
#pragma unroll
    for (int mt = 0; mt < 4; mt++)
        aRB[mt] = (uint32_t)((wm * 64 + mt * 16 + (lane & 15)) * 128 + ((lane >> 4) << 4));
#pragma unroll
    for (int hf = 0; hf < 2; hf++)
        bRB[hf] = (uint32_t)((wn * 32 + hf * 16 + ((lane >> 4) << 3) + (lane & 7)) * 128
                             + (((lane >> 3) & 1) << 4));

    for (int it = 0; it < NIT; it++) {
        if (it == NIT - 1) asm volatile("cp.async.wait_group 0;");
        else               asm volatile("cp.async.wait_group 1;");
        __syncthreads();

        uint32_t stage = sbase + (uint32_t)(it & 1) * STAGE_B;
        uint32_t sAh = stage, sAl = stage + TILE_B;
        uint32_t sBh = stage + 2 * TILE_B, sBl = stage + 3 * TILE_B;

#pragma unroll
        for (int ks = 0; ks < 4; ks++) {
            const uint32_t kb = (uint32_t)(ks * 32);
            uint32_t ah[4][4], al[4][4], bh[4][2], bl[4][2];
#pragma unroll
            for (int mt = 0; mt < 4; mt++) {
                ldsm_x4(ah[mt][0], ah[mt][1], ah[mt][2], ah[mt][3], sAh + SWZ(aRB[mt] + kb));
                ldsm_x4(al[mt][0], al[mt][1], al[mt][2], al[mt][3], sAl + SWZ(aRB[mt] + kb));
            }
#pragma unroll
            for (int hf = 0; hf < 2; hf++) {
                ldsm_x4(bh[hf*2][0], bh[hf*2][1], bh[hf*2+1][0], bh[hf*2+1][1],
                        sBh + SWZ(bRB[hf] + kb));
                ldsm_x4(bl[hf*2][0], bl[hf*2][1], bl[hf*2+1][0], bl[hf*2+1][1],
                        sBl + SWZ(bRB[hf] + kb));
            }
#pragma unroll
            for (int mt = 0; mt < 4; mt++)
#pragma unroll
                for (int nt = 0; nt < 4; nt++) {
                    mma16816(acc[mt][nt], ah[mt], bh[nt]);
                    mma16816(acc[mt][nt], ah[mt], bl[nt]);
                    mma16816(acc[mt][nt], al[mt], bh[nt]);
                }
        }
        __syncthreads();
        if (it + 2 < NIT) load_stage(it + 2);
    }

    // ---- epilogue ----
    const int rbase = m0 + wm * 64 + (lane >> 2);
    const int cbase = n0 + wn * 32 + (lane & 3) * 2;
#pragma unroll
    for (int mt = 0; mt < 4; mt++) {
#pragma unroll
        for (int nt = 0; nt < 4; nt++) {
            const int col = cbase + nt * 8;
            float2 bsv = *(const float2*)(bias + col);
            const int r0g = rbase + mt * 16;
            float2 o0 = make_float2(acc[mt][nt][0] + bsv.x, acc[mt][nt][1] + bsv.y);
            float2 o1 = make_float2(acc[mt][nt][2] + bsv.x, acc[mt][nt][3] + bsv.y);
            *(float2*)(C + (size_t)r0g * ldc + col) = o0;
            *(float2*)(C + (size_t)(r0g + 8) * ldc + col) = o1;
        }
    }
}

// ---------------- conversion kernels ----------------
__global__ void __launch_bounds__(256) conv_x_kernel(const float* __restrict__ x)
{
    int i = blockIdx.x * 256 + threadIdx.x;   // float4 index; total 1M
    float4 v = ((const float4*)x)[i];
    __nv_bfloat16 h0 = __float2bfloat16_rn(v.x);
    __nv_bfloat16 h1 = __float2bfloat16_rn(v.y);
    __nv_bfloat16 h2 = __float2bfloat16_rn(v.z);
    __nv_bfloat16 h3 = __float2bfloat16_rn(v.w);
    __nv_bfloat16 l0 = __float2bfloat16_rn(v.x - __bfloat162float(h0));
    __nv_bfloat16 l1 = __float2bfloat16_rn(v.y - __bfloat162float(h1));
    __nv_bfloat16 l2 = __float2bfloat16_rn(v.z - __bfloat162float(h2));
    __nv_bfloat16 l3 = __float2bfloat16_rn(v.w - __bfloat162float(h3));
    __nv_bfloat162* H = (__nv_bfloat162*)g_xh;
    __nv_bfloat162* L = (__nv_bfloat162*)g_xl;
    H[2 * i + 0] = __halves2bfloat162(h0, h1);
    H[2 * i + 1] = __halves2bfloat162(h2, h3);
    L[2 * i + 0] = __halves2bfloat162(l0, l1);
    L[2 * i + 1] = __halves2bfloat162(l2, l3);
}

// transpose + split W[k][n] -> Wt[n][k] hi/lo (z selects Wq/Wk/Wv/Wo)
__global__ void __launch_bounds__(256) conv_w_kernel(
    const float* __restrict__ Wq, const float* __restrict__ Wk,
    const float* __restrict__ Wv, const float* __restrict__ Wo)
{
    __shared__ float t[32][33];
    const int z = blockIdx.z;
    const float* src = (z == 0) ? Wq : (z == 1) ? Wk : (z == 2) ? Wv : Wo;
    __nv_bfloat16* dh = (z < 3) ? (g_Wth + (size_t)z * DM * DM) : g_Woth;
    __nv_bfloat16* dl = (z < 3) ? (g_Wtl + (size_t)z * DM * DM) : g_Wotl;
    const int n0 = blockIdx.x * 32, k0 = blockIdx.y * 32;
    const int tx = threadIdx.x & 31, ty = threadIdx.x >> 5;
#pragma unroll
    for (int rr = 0; rr < 4; rr++) {
        int r = ty + rr * 8;
        t[r][tx] = src[(size_t)(k0 + r) * DM + n0 + tx];
    }
    __syncthreads();
#pragma unroll
    for (int rr = 0; rr < 4; rr++) {
        int r = ty + rr * 8;                 // n-local
        float v = t[tx][r];                  // = src[k0+tx][n0+r]
        __nv_bfloat16 h = __float2bfloat16_rn(v);
        __nv_bfloat16 l = __float2bfloat16_rn(v - __bfloat162float(h));
        dh[(size_t)(n0 + r) * DM + k0 + tx] = h;
        dl[(size_t)(n0 + r) * DM + k0 + tx] = l;
    }
}

__global__ void __launch_bounds__(256) pack_bias_kernel(
    const float* __restrict__ bq, const float* __restrict__ bk, const float* __restrict__ bv)
{
    int i = blockIdx.x * 256 + threadIdx.x;
    float v = (i < DM) ? bq[i] : (i < 2 * DM) ? bk[i - DM] : bv[i - 2 * DM];
    g_biasqkv[i] = v;
}

// ---------------- linear-attention middle path ----------------
__global__ void __launch_bounds__(256) kv_partial_kernel()
{
    const int bh = blockIdx.x;     // 0..31
    const int ls = blockIdx.y;     // 0..7
    const int b = bh >> 4, h = bh & 15;

    __shared__ float Ks[64][65];
    __shared__ float Vs[64][65];

    const int tid = threadIdx.x;
    const int tx = tid & 15, ty = tid >> 4;

    const float* Kb = g_QKV + (size_t)b * LL * NQKV + DM + h * HD;
    const float* Vb = Kb + DM;

    float acc[4][4];
#pragma unroll
    for (int i = 0; i < 4; i++)
#pragma unroll
        for (int j = 0; j < 4; j++) acc[i][j] = 0.f;

    for (int l0 = ls * 256; l0 < ls * 256 + 256; l0 += 64) {
#pragma unroll
        for (int t = 0; t < 4; t++) {
            int idx = tid + t * 256;
            int r = idx >> 4;
            int c = (idx & 15) * 4;
            float4 kv = *(const float4*)(Kb + (size_t)(l0 + r) * NQKV + c);
            Ks[r][c + 0] = kv.x; Ks[r][c + 1] = kv.y;
            Ks[r][c + 2] = kv.z; Ks[r][c + 3] = kv.w;
            float4 vv = *(const float4*)(Vb + (size_t)(l0 + r) * NQKV + c);
            Vs[r][c + 0] = vv.x; Vs[r][c + 1] = vv.y;
            Vs[r][c + 2] = vv.z; Vs[r][c + 3] = vv.w;
        }
        __syncthreads();
#pragma unroll 8
        for (int l = 0; l < 64; l++) {
            float kr[4], vr[4];
#pragma unroll
            for (int i = 0; i < 4; i++) kr[i] = Ks[l][ty * 4 + i];
#pragma unroll
            for (int j = 0; j < 4; j++) vr[j] = Vs[l][tx * 4 + j];
#pragma unroll
            for (int i = 0; i < 4; i++)
#pragma unroll
                for (int j = 0; j < 4; j++)
                    acc[i][j] = fmaf(kr[i], vr[j], acc[i][j]);
        }
        __syncthreads();
    }

    float* Mo = g_Mp + ((size_t)ls * 32 + bh) * (HD * HD);
#pragma unroll
    for (int i = 0; i < 4; i++)
#pragma unroll
        for (int j = 0; j < 4; j++)
            Mo[(ty * 4 + i) * HD + tx * 4 + j] = acc[i][j];
}

__global__ void __launch_bounds__(256) kv_reduce_kernel()
{
    const int bh = blockIdx.x;
    for (int e = threadIdx.x; e < HD * HD; e += 256) {
        float s = 0.f;
#pragma unroll
        for (int ls = 0; ls < 8; ls++)
            s += g_Mp[((size_t)ls * 32 + bh) * (HD * HD) + e];
        g_M[(size_t)bh * (HD * HD) + e] = s * 0.125f;   // 1/sqrt(64)
    }
}

// attn[b,l,h,:] = Q[b,l,h,:] @ M[b,h]; write bf16 hi/lo directly
__global__ void __launch_bounds__(256) attn_apply_kernel()
{
    const int bh = blockIdx.y;
    const int b = bh >> 4, h = bh & 15;
    const int l0 = blockIdx.x * 64;

    __shared__ float Ms[64][65];
    __shared__ float Qs[64][65];

    const int tid = threadIdx.x;
    const float* Mg = g_M + (size_t)bh * (HD * HD);
    const float* Qb = g_QKV + ((size_t)b * LL + l0) * NQKV + h * HD;

#pragma unroll
    for (int t = 0; t < 4; t++) {
        int idx = tid + t * 256;
        int r = idx >> 4;
        int c = (idx & 15) * 4;
        float4 mv = *(const float4*)(Mg + r * HD + c);
        Ms[r][c + 0] = mv.x; Ms[r][c + 1] = mv.y;
        Ms[r][c + 2] = mv.z; Ms[r][c + 3] = mv.w;
        float4 qv = *(const float4*)(Qb + (size_t)r * NQKV + c);
        Qs[r][c + 0] = qv.x; Qs[r][c + 1] = qv.y;
        Qs[r][c + 2] = qv.z; Qs[r][c + 3] = qv.w;
    }
    __syncthreads();

    const int row = tid >> 2;
    const int c0 = (tid & 3) * 16;

    float acc[16];
#pragma unroll
    for (int j = 0; j < 16; j++) acc[j] = 0.f;

#pragma unroll 8
    for (int k = 0; k < 64; k++) {
        float q = Qs[row][k];
#pragma unroll
        for (int j = 0; j < 16; j++)
            acc[j] = fmaf(q, Ms[k][c0 + j], acc[j]);
    }

    size_t ofs = ((size_t)b * LL + l0 + row) * DM + h * HD + c0;
    __nv_bfloat162* Ah2 = (__nv_bfloat162*)(g_ah + ofs);
    __nv_bfloat162* Al2 = (__nv_bfloat162*)(g_al + ofs);
#pragma unroll
    for (int j = 0; j < 16; j += 2) {
        __nv_bfloat16 h0 = __float2bfloat16_rn(acc[j]);
        __nv_bfloat16 h1 = __float2bfloat16_rn(acc[j + 1]);
        __nv_bfloat16 lo0 = __float2bfloat16_rn(acc[j] - __bfloat162float(h0));
        __nv_bfloat16 lo1 = __float2bfloat16_rn(acc[j + 1] - __bfloat162float(h1));
        Ah2[j >> 1] = __halves2bfloat162(h0, h1);
        Al2[j >> 1] = __halves2bfloat162(lo0, lo1);
    }
}

// ---------------- launch ----------------
extern "C" void kernel_launch(void* const* d_in, const int* in_sizes, int n_in,
                              void* d_out, int out_size)
{
    (void)in_sizes; (void)n_in; (void)out_size;
    const float* x  = (const float*)d_in[0];
    const float* Wq = (const float*)d_in[1];
    const float* bq = (const float*)d_in[2];
    const float* Wk = (const float*)d_in[3];
    const float* bk = (const float*)d_in[4];
    const float* Wv = (const float*)d_in[5];
    const float* bv = (const float*)d_in[6];
    const float* Wo = (const float*)d_in[7];
    const float* bo = (const float*)d_in[8];
    float* out = (float*)d_out;

    __nv_bfloat16 *xh, *xl, *Wth, *Wtl, *Woth, *Wotl, *ah, *al;
    float *QKV, *biasqkv;
    cudaGetSymbolAddress((void**)&xh, g_xh);
    cudaGetSymbolAddress((void**)&xl, g_xl);
    cudaGetSymbolAddress((void**)&Wth, g_Wth);
    cudaGetSymbolAddress((void**)&Wtl, g_Wtl);
    cudaGetSymbolAddress((void**)&Woth, g_Woth);
    cudaGetSymbolAddress((void**)&Wotl, g_Wotl);
    cudaGetSymbolAddress((void**)&QKV, g_QKV);
    cudaGetSymbolAddress((void**)&biasqkv, g_biasqkv);
    cudaGetSymbolAddress((void**)&ah, g_ah);
    cudaGetSymbolAddress((void**)&al, g_al);

    cudaFuncSetAttribute(gemm_bf16x3, cudaFuncAttributeMaxDynamicSharedMemorySize,
                         SMEM_GEMM_TOTAL);

    // hi/lo conversions
    conv_x_kernel<<<ROWS * DM / 4 / 256, 256>>>(x);
    conv_w_kernel<<<dim3(32, 32, 4), 256>>>(Wq, Wk, Wv, Wo);
    pack_bias_kernel<<<NQKV / 256, 256>>>(bq, bk, bv);

    // fused QKV projection: [4096,1024] @ [1024,3072]
    gemm_bf16x3<<<dim3(NQKV / 128, ROWS / 128), 256, SMEM_GEMM_TOTAL>>>(
        xh, xl, Wth, Wtl, biasqkv, QKV, NQKV);

    // linear attention middle path
    kv_partial_kernel<<<dim3(32, 8), 256>>>();
    kv_reduce_kernel<<<32, 256>>>();
    attn_apply_kernel<<<dim3(LL / 64, BB * NH), 256>>>();

    // output projection: attn @ Wo + bo -> out
    gemm_bf16x3<<<dim3(DM / 128, ROWS / 128), 256, SMEM_GEMM_TOTAL>>>(
        ah, al, Woth, Wotl, bo, out, DM);
}

// round 11
// speedup vs baseline: 2.7179x; 1.0051x over previous
#include <cuda_runtime.h>
#include <cuda_bf16.h>
#include <cstdint>

#define BB 2
#define LL 2048
#define DM 1024
#define NH 16
#define HD 64
#define ROWS (BB*LL)      /* 4096 */
#define NQKV (3*DM)       /* 3072 */

// ---------------- device scratch (allocation-free rule) ----------------
__device__ __nv_bfloat16 g_xh[ROWS*DM];
__device__ __nv_bfloat16 g_xl[ROWS*DM];
__device__ __nv_bfloat16 g_Wth[NQKV*DM];   // [Wq^T;Wk^T;Wv^T] as [n][k]
__device__ __nv_bfloat16 g_Wtl[NQKV*DM];
__device__ __nv_bfloat16 g_Woth[DM*DM];    // Wo^T [n][k]
__device__ __nv_bfloat16 g_Wotl[DM*DM];
__device__ float g_QKV[ROWS*NQKV];         // fused QKV output, fp32
__device__ float g_biasqkv[NQKV];
__device__ float g_Mp[8*BB*NH*HD*HD];      // kv partials [ls][bh][64][64]
__device__ float g_M[BB*NH*HD*HD];
__device__ __nv_bfloat16 g_ah[ROWS*DM];    // attn hi/lo
__device__ __nv_bfloat16 g_al[ROWS*DM];

// ---------------- helpers ----------------
__device__ __forceinline__ uint32_t s2u(const void* p) {
    uint32_t a;
    asm("{ .reg .u64 t; cvta.to.shared.u64 t, %1; cvt.u32.u64 %0, t; }" : "=r"(a) : "l"(p));
    return a;
}
#define SWZ(x) ((x) ^ (((x) >> 3) & 0x70))

__device__ __forceinline__ void cpa16(uint32_t dst, const void* src) {
    asm volatile("cp.async.cg.shared.global [%0], [%1], 16;" :: "r"(dst), "l"(src));
}

__device__ __forceinline__ void ldsm_x4(uint32_t& r0, uint32_t& r1, uint32_t& r2,
                                        uint32_t& r3, uint32_t addr) {
    asm volatile("ldmatrix.sync.aligned.m8n8.x4.shared.b16 {%0,%1,%2,%3}, [%4];"
                 : "=r"(r0), "=r"(r1), "=r"(r2), "=r"(r3) : "r"(addr));
}

__device__ __forceinline__ void mma16816(float* d, const uint32_t* a, const uint32_t* b) {
    asm volatile(
        "mma.sync.aligned.m16n8k16.row.col.f32.bf16.bf16.f32 "
        "{%0,%1,%2,%3}, {%4,%5,%6,%7}, {%8,%9}, {%0,%1,%2,%3};"
        : "+f"(d[0]), "+f"(d[1]), "+f"(d[2]), "+f"(d[3])
        : "r"(a[0]), "r"(a[1]), "r"(a[2]), "r"(a[3]), "r"(b[0]), "r"(b[1]));
}

// ---------------- bf16x3 HMMA GEMM ----------------
// C[M,N] = Ah@Bh^T + Ah@Bl^T + Al@Bh^T + bias, fp32 out.
// A: [M][1024] bf16 row-major; B: [N][1024] bf16 row-major (N rows, K cols).
// CTA 128x128, BK=64, 8 warps (2x4), warp tile 64x32.
// 3-stage cp.async ring, ONE __syncthreads per iteration, loads issued
// before compute so each stage has a full compute block to land in.
#define TILE_B 16384u                       /* 128 rows x 128 bytes */
#define STAGE_B (4u*TILE_B)                 /* Ah, Al, Bh, Bl = 64KB */
#define NSTAGE 3
#define SMEM_GEMM_TOTAL (NSTAGE*STAGE_B)    /* 196608 */
#define NIT 16

__global__ void __launch_bounds__(256, 1)
gemm_bf16x3(const __nv_bfloat16* __restrict__ Ah, const __nv_bfloat16* __restrict__ Al,
            const __nv_bfloat16* __restrict__ Bh, const __nv_bfloat16* __restrict__ Bl,
            const float* __restrict__ bias, float* __restrict__ C, int ldc)
{
    extern __shared__ char smem[];
    const uint32_t sbase = s2u(smem);
    const int tid = threadIdx.x;
    const int wid = tid >> 5, lane = tid & 31;
    const int wm = wid >> 2;          // 0..1 (m)
    const int wn = wid & 3;           // 0..3 (n)
    const int m0 = blockIdx.y * 128;
    const int n0 = blockIdx.x * 128;

    // ---- stage loader: 4 tiles (Ah, Al, Bh, Bl), 16 cp.async per thread ----
    auto load_stage = [&](int it) {
        uint32_t stage = sbase + (uint32_t)(it % NSTAGE) * STAGE_B;
        const int k0 = it * 64;
        const __nv_bfloat16* bases[4] = {Ah, Al, Bh, Bl};
        const int r0[4] = {m0, m0, n0, n0};
#pragma unroll
        for (int t = 0; t < 4; t++) {
#pragma unroll
            for (int j = 0; j < 4; j++) {
                int u = tid + j * 256;          // 0..1023 16B-chunks
                int row = u >> 3;
                int cb = (u & 7) * 16;          // byte col within 128B row
                const char* src = (const char*)(bases[t] + (size_t)(r0[t] + row) * DM + k0)
                                  + cb;
                uint32_t dst = stage + (uint32_t)t * TILE_B + SWZ((uint32_t)(row * 128 + cb));
                cpa16(dst, src);
            }
        }
        asm volatile("cp.async.commit_group;");
    };

    load_stage(0);
    load_stage(1);

    float acc[4][4][4];
#pragma unroll
    for (int i = 0; i < 4; i++)
#pragma unroll
        for (int j = 0; j < 4; j++)
#pragma unroll
            for (int e = 0; e < 4; e++) acc[i][j][e] = 0.f;

    // precompute per-lane row-byte offsets (k-independent part)
    uint32_t aRB[4], bRB[2];
#pragma unroll
    for (int mt = 0; mt < 4; mt++)
        aRB[mt] = (uint32_t)((wm * 64 + mt * 16 + (lane & 15)) * 128 + ((lane >> 4) << 4));
#pragma unroll
    for (int hf = 0; hf < 2; hf++)
        bRB[hf] = (uint32_t)((wn * 32 + hf * 16 + ((lane >> 4) << 3) + (lane & 7)) * 128
                             + (((lane >> 3) & 1) << 4));

    for (int it = 0; it < NIT; it++) {
        if (it == NIT - 1) asm volatile("cp.async.wait_group 0;");
        else               asm volatile("cp.async.wait_group 1;");
        __syncthreads();   // single barrier: stage `it` ready; buffer (it+2)%3 free

        // issue next loads FIRST so they overlap this iteration's compute
        if (it + 2 < NIT) load_stage(it + 2);

        uint32_t stage = sbase + (uint32_t)(it % NSTAGE) * STAGE_B;
        uint32_t sAh = stage, sAl = stage + TILE_B;
        uint32_t sBh = stage + 2 * TILE_B, sBl = stage + 3 * TILE_B;

#pragma unroll
        for (int ks = 0; ks < 4; ks++) {
            const uint32_t kb = (uint32_t)(ks * 32);
            uint32_t ah[4][4], al[4][4], bh[4][2], bl[4][2];
#pragma unroll
            for (int mt = 0; mt < 4; mt++) {
                ldsm_x4(ah[mt][0], ah[mt][1], ah[mt][2], ah[mt][3], sAh + SWZ(aRB[mt] + kb));
                ldsm_x4(al[mt][0], al[mt][1], al[mt][2], al[mt][3], sAl + SWZ(aRB[mt] + kb));
            }
#pragma unroll
            for (int hf = 0; hf < 2; hf++) {
                ldsm_x4(bh[hf*2][0], bh[hf*2][1], bh[hf*2+1][0], bh[hf*2+1][1],
                        sBh + SWZ(bRB[hf] + kb));
                ldsm_x4(bl[hf*2][0], bl[hf*2][1], bl[hf*2+1][0], bl[hf*2+1][1],
                        sBl + SWZ(bRB[hf] + kb));
            }
#pragma unroll
            for (int mt = 0; mt < 4; mt++)
#pragma unroll
                for (int nt = 0; nt < 4; nt++) {
                    mma16816(acc[mt][nt], ah[mt], bh[nt]);
                    mma16816(acc[mt][nt], ah[mt], bl[nt]);
                    mma16816(acc[mt][nt], al[mt], bh[nt]);
                }
        }
        // no trailing barrier: next iteration's barrier (after its wait)
        // protects buffer reuse — reads of stage `it` finished by then.
    }

    // ---- epilogue ----
    const int rbase = m0 + wm * 64 + (lane >> 2);
    const int cbase = n0 + wn * 32 + (lane & 3) * 2;
#pragma unroll
    for (int mt = 0; mt < 4; mt++) {
#pragma unroll
        for (int nt = 0; nt < 4; nt++) {
            const int col = cbase + nt * 8;
            float2 bsv = *(const float2*)(bias + col);
            const int r0g = rbase + mt * 16;
            float2 o0 = make_float2(acc[mt][nt][0] + bsv.x, acc[mt][nt][1] + bsv.y);
            float2 o1 = make_float2(acc[mt][nt][2] + bsv.x, acc[mt][nt][3] + bsv.y);
            *(float2*)(C + (size_t)r0g * ldc + col) = o0;
            *(float2*)(C + (size_t)(r0g + 8) * ldc + col) = o1;
        }
    }
}

// ---------------- conversion kernels ----------------
__global__ void __launch_bounds__(256) conv_x_kernel(const float* __restrict__ x)
{
    int i = blockIdx.x * 256 + threadIdx.x;   // float4 index; total 1M
    float4 v = ((const float4*)x)[i];
    __nv_bfloat16 h0 = __float2bfloat16_rn(v.x);
    __nv_bfloat16 h1 = __float2bfloat16_rn(v.y);
    __nv_bfloat16 h2 = __float2bfloat16_rn(v.z);
    __nv_bfloat16 h3 = __float2bfloat16_rn(v.w);
    __nv_bfloat16 l0 = __float2bfloat16_rn(v.x - __bfloat162float(h0));
    __nv_bfloat16 l1 = __float2bfloat16_rn(v.y - __bfloat162float(h1));
    __nv_bfloat16 l2 = __float2bfloat16_rn(v.z - __bfloat162float(h2));
    __nv_bfloat16 l3 = __float2bfloat16_rn(v.w - __bfloat162float(h3));
    __nv_bfloat162* H = (__nv_bfloat162*)g_xh;
    __nv_bfloat162* L = (__nv_bfloat162*)g_xl;
    H[2 * i + 0] = __halves2bfloat162(h0, h1);
    H[2 * i + 1] = __halves2bfloat162(h2, h3);
    L[2 * i + 0] = __halves2bfloat162(l0, l1);
    L[2 * i + 1] = __halves2bfloat162(l2, l3);
}

// transpose + split W[k][n] -> Wt[n][k] hi/lo (z selects Wq/Wk/Wv/Wo)
__global__ void __launch_bounds__(256) conv_w_kernel(
    const float* __restrict__ Wq, const float* __restrict__ Wk,
    const float* __restrict__ Wv, const float* __restrict__ Wo)
{
    __shared__ float t[32][33];
    const int z = blockIdx.z;
    const float* src = (z == 0) ? Wq : (z == 1) ? Wk : (z == 2) ? Wv : Wo;
    __nv_bfloat16* dh = (z < 3) ? (g_Wth + (size_t)z * DM * DM) : g_Woth;
    __nv_bfloat16* dl = (z < 3) ? (g_Wtl + (size_t)z * DM * DM) : g_Wotl;
    const int n0 = blockIdx.x * 32, k0 = blockIdx.y * 32;
    const int tx = threadIdx.x & 31, ty = threadIdx.x >> 5;
#pragma unroll
    for (int rr = 0; rr < 4; rr++) {
        int r = ty + rr * 8;
        t[r][tx] = src[(size_t)(k0 + r) * DM + n0 + tx];
    }
    __syncthreads();
#pragma unroll
    for (int rr = 0; rr < 4; rr++) {
        int r = ty + rr * 8;                 // n-local
        float v = t[tx][r];                  // = src[k0+tx][n0+r]
        __nv_bfloat16 h = __float2bfloat16_rn(v);
        __nv_bfloat16 l = __float2bfloat16_rn(v - __bfloat162float(h));
        dh[(size_t)(n0 + r) * DM + k0 + tx] = h;
        dl[(size_t)(n0 + r) * DM + k0 + tx] = l;
    }
}

__global__ void __launch_bounds__(256) pack_bias_kernel(
    const float* __restrict__ bq, const float* __restrict__ bk, const float* __restrict__ bv)
{
    int i = blockIdx.x * 256 + threadIdx.x;
    float v = (i < DM) ? bq[i] : (i < 2 * DM) ? bk[i - DM] : bv[i - 2 * DM];
    g_biasqkv[i] = v;
}

// ---------------- linear-attention middle path ----------------
__global__ void __launch_bounds__(256) kv_partial_kernel()
{
    const int bh = blockIdx.x;     // 0..31
    const int ls = blockIdx.y;     // 0..7
    const int b = bh >> 4, h = bh & 15;

    __shared__ float Ks[64][65];
    __shared__ float Vs[64][65];

    const int tid = threadIdx.x;
    const int tx = tid & 15, ty = tid >> 4;

    const float* Kb = g_QKV + (size_t)b * LL * NQKV + DM + h * HD;
    const float* Vb = Kb + DM;

    float acc[4][4];
#pragma unroll
    for (int i = 0; i < 4; i++)
#pragma unroll
        for (int j = 0; j < 4; j++) acc[i][j] = 0.f;

    for (int l0 = ls * 256; l0 < ls * 256 + 256; l0 += 64) {
#pragma unroll
        for (int t = 0; t < 4; t++) {
            int idx = tid + t * 256;
            int r = idx >> 4;
            int c = (idx & 15) * 4;
            float4 kv = *(const float4*)(Kb + (size_t)(l0 + r) * NQKV + c);
            Ks[r][c + 0] = kv.x; Ks[r][c + 1] = kv.y;
            Ks[r][c + 2] = kv.z; Ks[r][c + 3] = kv.w;
            float4 vv = *(const float4*)(Vb + (size_t)(l0 + r) * NQKV + c);
            Vs[r][c + 0] = vv.x; Vs[r][c + 1] = vv.y;
            Vs[r][c + 2] = vv.z; Vs[r][c + 3] = vv.w;
        }
        __syncthreads();
#pragma unroll 8
        for (int l = 0; l < 64; l++) {
            float kr[4], vr[4];
#pragma unroll
            for (int i = 0; i < 4; i++) kr[i] = Ks[l][ty * 4 + i];
#pragma unroll
            for (int j = 0; j < 4; j++) vr[j] = Vs[l][tx * 4 + j];
#pragma unroll
            for (int i = 0; i < 4; i++)
#pragma unroll
                for (int j = 0; j < 4; j++)
                    acc[i][j] = fmaf(kr[i], vr[j], acc[i][j]);
        }
        __syncthreads();
    }

    float* Mo = g_Mp + ((size_t)ls * 32 + bh) * (HD * HD);
#pragma unroll
    for (int i = 0; i < 4; i++)
#pragma unroll
        for (int j = 0; j < 4; j++)
            Mo[(ty * 4 + i) * HD + tx * 4 + j] = acc[i][j];
}

__global__ void __launch_bounds__(256) kv_reduce_kernel()
{
    const int bh = blockIdx.x;
    for (int e = threadIdx.x; e < HD * HD; e += 256) {
        float s = 0.f;
#pragma unroll
        for (int ls = 0; ls < 8; ls++)
            s += g_Mp[((size_t)ls * 32 + bh) * (HD * HD) + e];
        g_M[(size_t)bh * (HD * HD) + e] = s * 0.125f;   // 1/sqrt(64)
    }
}

// attn[b,l,h,:] = Q[b,l,h,:] @ M[b,h]; write bf16 hi/lo directly
__global__ void __launch_bounds__(256) attn_apply_kernel()
{
    const int bh = blockIdx.y;
    const int b = bh >> 4, h = bh & 15;
    const int l0 = blockIdx.x * 64;

    __shared__ float Ms[64][65];
    __shared__ float Qs[64][65];

    const int tid = threadIdx.x;
    const float* Mg = g_M + (size_t)bh * (HD * HD);
    const float* Qb = g_QKV + ((size_t)b * LL + l0) * NQKV + h * HD;

#pragma unroll
    for (int t = 0; t < 4; t++) {
        int idx = tid + t * 256;
        int r = idx >> 4;
        int c = (idx & 15) * 4;
        float4 mv = *(const float4*)(Mg + r * HD + c);
        Ms[r][c + 0] = mv.x; Ms[r][c + 1] = mv.y;
        Ms[r][c + 2] = mv.z; Ms[r][c + 3] = mv.w;
        float4 qv = *(const float4*)(Qb + (size_t)r * NQKV + c);
        Qs[r][c + 0] = qv.x; Qs[r][c + 1] = qv.y;
        Qs[r][c + 2] = qv.z; Qs[r][c + 3] = qv.w;
    }
    __syncthreads();

    const int row = tid >> 2;
    const int c0 = (tid & 3) * 16;

    float acc[16];
#pragma unroll
    for (int j = 0; j < 16; j++) acc[j] = 0.f;

#pragma unroll 8
    for (int k = 0; k < 64; k++) {
        float q = Qs[row][k];
#pragma unroll
        for (int j = 0; j < 16; j++)
            acc[j] = fmaf(q, Ms[k][c0 + j], acc[j]);
    }

    size_t ofs = ((size_t)b * LL + l0 + row) * DM + h * HD + c0;
    __nv_bfloat162* Ah2 = (__nv_bfloat162*)(g_ah + ofs);
    __nv_bfloat162* Al2 = (__nv_bfloat162*)(g_al + ofs);
#pragma unroll
    for (int j = 0; j < 16; j += 2) {
        __nv_bfloat16 h0 = __float2bfloat16_rn(acc[j]);
        __nv_bfloat16 h1 = __float2bfloat16_rn(acc[j + 1]);
        __nv_bfloat16 lo0 = __float2bfloat16_rn(acc[j] - __bfloat162float(h0));
        __nv_bfloat16 lo1 = __float2bfloat16_rn(acc[j + 1] - __bfloat162float(h1));
        Ah2[j >> 1] = __halves2bfloat162(h0, h1);
        Al2[j >> 1] = __halves2bfloat162(lo0, lo1);
    }
}

// ---------------- launch ----------------
extern "C" void kernel_launch(void* const* d_in, const int* in_sizes, int n_in,
                              void* d_out, int out_size)
{
    (void)in_sizes; (void)n_in; (void)out_size;
    const float* x  = (const float*)d_in[0];
    const float* Wq = (const float*)d_in[1];
    const float* bq = (const float*)d_in[2];
    const float* Wk = (const float*)d_in[3];
    const float* bk = (const float*)d_in[4];
    const float* Wv = (const float*)d_in[5];
    const float* bv = (const float*)d_in[6];
    const float* Wo = (const float*)d_in[7];
    const float* bo = (const float*)d_in[8];
    float* out = (float*)d_out;

    __nv_bfloat16 *xh, *xl, *Wth, *Wtl, *Woth, *Wotl, *ah, *al;
    float *QKV, *biasqkv;
    cudaGetSymbolAddress((void**)&xh, g_xh);
    cudaGetSymbolAddress((void**)&xl, g_xl);
    cudaGetSymbolAddress((void**)&Wth, g_Wth);
    cudaGetSymbolAddress((void**)&Wtl, g_Wtl);
    cudaGetSymbolAddress((void**)&Woth, g_Woth);
    cudaGetSymbolAddress((void**)&Wotl, g_Wotl);
    cudaGetSymbolAddress((void**)&QKV, g_QKV);
    cudaGetSymbolAddress((void**)&biasqkv, g_biasqkv);
    cudaGetSymbolAddress((void**)&ah, g_ah);
    cudaGetSymbolAddress((void**)&al, g_al);

    cudaFuncSetAttribute(gemm_bf16x3, cudaFuncAttributeMaxDynamicSharedMemorySize,
                         SMEM_GEMM_TOTAL);

    // hi/lo conversions
    conv_x_kernel<<<ROWS * DM / 4 / 256, 256>>>(x);
    conv_w_kernel<<<dim3(32, 32, 4), 256>>>(Wq, Wk, Wv, Wo);
    pack_bias_kernel<<<NQKV / 256, 256>>>(bq, bk, bv);

    // fused QKV projection: [4096,1024] @ [1024,3072]
    gemm_bf16x3<<<dim3(NQKV / 128, ROWS / 128), 256, SMEM_GEMM_TOTAL>>>(
        xh, xl, Wth, Wtl, biasqkv, QKV, NQKV);

    // linear attention middle path
    kv_partial_kernel<<<dim3(32, 8), 256>>>();
    kv_reduce_kernel<<<32, 256>>>();
    attn_apply_kernel<<<dim3(LL / 64, BB * NH), 256>>>();

    // output projection: attn @ Wo + bo -> out
    gemm_bf16x3<<<dim3(DM / 128, ROWS / 128), 256, SMEM_GEMM_TOTAL>>>(
        ah, al, Woth, Wotl, bo, out, DM);
}